// round 4
// baseline (speedup 1.0000x reference)
#include <cuda_runtime.h>
#include <cstdint>

// Problem dims
#define NB 8192   // tokens
#define NF 2048   // features (= K of every GEMM here)
#define NE 16     // experts
#define NU 2048   // expert hidden / d_model
#define NDM 2048
#define NH 16
#define NDEPTH 128

// ---------------- device scratch (no allocations allowed) ----------------
__device__ float g_moe[(size_t)NB * NU];
__device__ float g_q [(size_t)NB * NDM];
__device__ float g_k [(size_t)NB * NDM];
__device__ float g_v [(size_t)NB * NDM];
__device__ float g_att[(size_t)NB * NDM];
__device__ int   g_counts[NE];
__device__ int   g_rows [NE * NB];
__device__ float g_gates[NE * NB];

// ---------------- small helpers ----------------
__device__ __forceinline__ uint32_t f2tf(float x) {
    uint32_t r;
    asm("cvt.rna.tf32.f32 %0, %1;" : "=r"(r) : "f"(x));
    return r;
}

__device__ __forceinline__ void mma8(float* c, const uint32_t* a, const uint32_t* b) {
    asm volatile(
        "mma.sync.aligned.m16n8k8.row.col.f32.tf32.tf32.f32 "
        "{%0,%1,%2,%3},{%4,%5,%6,%7},{%8,%9},{%0,%1,%2,%3};"
        : "+f"(c[0]), "+f"(c[1]), "+f"(c[2]), "+f"(c[3])
        : "r"(a[0]), "r"(a[1]), "r"(a[2]), "r"(a[3]), "r"(b[0]), "r"(b[1]));
}

__device__ __forceinline__ uint32_t smem_u32(const void* p) {
    return (uint32_t)__cvta_generic_to_shared(p);
}

#define CPA16(dst, src) \
    asm volatile("cp.async.cg.shared.global [%0], [%1], 16;" :: "r"(dst), "l"(src))

// ---------------- zero scratch + counts ----------------
__global__ void zero_kernel() {
    size_t n = (size_t)NB * NU / 4;
    float4* p = (float4*)g_moe;
    float4 z = make_float4(0.f, 0.f, 0.f, 0.f);
    for (size_t i = (size_t)blockIdx.x * blockDim.x + threadIdx.x; i < n;
         i += (size_t)gridDim.x * blockDim.x)
        p[i] = z;
    if (blockIdx.x == 0 && threadIdx.x < NE) g_counts[threadIdx.x] = 0;
}

// ---------------- router: fp32 logits, softmax, top-2, token lists ----------------
__global__ void router_kernel(const float* __restrict__ x,
                              const float* __restrict__ rw,
                              const float* __restrict__ rb) {
    const int b = blockIdx.x;
    const int tid = threadIdx.x;  // 128 threads
    float part[NE];
#pragma unroll
    for (int e = 0; e < NE; e++) part[e] = 0.f;

    const float* xr = x + (size_t)b * NF;
    for (int f = tid; f < NF; f += 128) {
        float xv = xr[f];
        const float4* w4 = (const float4*)(rw + (size_t)f * NE);
#pragma unroll
        for (int e4 = 0; e4 < 4; e4++) {
            float4 w = w4[e4];
            part[e4 * 4 + 0] += xv * w.x;
            part[e4 * 4 + 1] += xv * w.y;
            part[e4 * 4 + 2] += xv * w.z;
            part[e4 * 4 + 3] += xv * w.w;
        }
    }

    __shared__ float red[NE][128];
#pragma unroll
    for (int e = 0; e < NE; e++) red[e][tid] = part[e];
    __syncthreads();

    __shared__ float lg[NE];
    if (tid < NE) {
        float s = 0.f;
        for (int j = 0; j < 128; j++) s += red[tid][j];
        lg[tid] = s + rb[tid];
    }
    __syncthreads();

    if (tid == 0) {
        float mx = lg[0];
#pragma unroll
        for (int e = 1; e < NE; e++) mx = fmaxf(mx, lg[e]);
        float p[NE];
        float s = 0.f;
#pragma unroll
        for (int e = 0; e < NE; e++) { p[e] = expf(lg[e] - mx); s += p[e]; }
        // top-1: strict > keeps first index on ties (matches jax top_k)
        int e0 = 0; float b0 = p[0];
#pragma unroll
        for (int e = 1; e < NE; e++) if (p[e] > b0) { b0 = p[e]; e0 = e; }
        int e1 = -1; float b1 = -1.f;
#pragma unroll
        for (int e = 0; e < NE; e++)
            if (e != e0 && p[e] > b1) { b1 = p[e]; e1 = e; }
        float inv = 1.f / s;
        int pos = atomicAdd(&g_counts[e0], 1);
        g_rows [e0 * NB + pos] = b;
        g_gates[e0 * NB + pos] = b0 * inv;
        pos = atomicAdd(&g_counts[e1], 1);
        g_rows [e1 * NB + pos] = b;
        g_gates[e1 * NB + pos] = b1 * inv;
    }
}

// ---------------- tf32 GEMM: 128x128x16 tiles, cp.async double buffer ----------------
#define BM 128
#define BN 128
#define BK 16
#define LDA (BK + 4)   // 20 floats -> 80B rows (16B aligned, LDS conflict-free)
#define LDB (BN + 8)   // 136 floats -> 544B rows (16B aligned, conflict-free)
#define NTHREADS 256
#define NKITER (NF / BK)  // 128

// MOE=true : A rows gathered via g_rows, epilogue gate*relu(acc+bias) atomicAdd-scattered
// MOE=false: plain C = A@W + bias
template <bool MOE>
__global__ __launch_bounds__(NTHREADS) void gemm_kernel(
    const float* __restrict__ A, const float* __restrict__ W,
    const float* __restrict__ bias, float* __restrict__ C) {
    __shared__ float As[2][BM][LDA];
    __shared__ float Bs[2][BK][LDB];
    __shared__ int rows_s[BM];
    __shared__ float gate_s[BM];

    const int tid = threadIdx.x;
    const int n0blk = blockIdx.x * BN;
    const int m0blk = blockIdx.y * BM;

    int cnt = BM;
    const float* Wp = W;
    const float* biasp = bias;
    if (MOE) {
        const int e = blockIdx.z;
        const int ce = g_counts[e];
        cnt = ce - m0blk;
        if (cnt <= 0) return;
        Wp = W + (size_t)e * NF * NU;
        biasp = bias + e * NU;
        if (tid < BM) {
            bool v = tid < cnt;
            rows_s[tid] = v ? g_rows [e * NB + m0blk + tid] : 0;
            gate_s[tid] = v ? g_gates[e * NB + m0blk + tid] : 0.f;
        }
        __syncthreads();
    }

    const int lane = tid & 31, warp = tid >> 5;
    const int wm = (warp >> 2) * 64;
    const int wn = (warp & 3) * 32;
    const int g = lane >> 2, tig = lane & 3;

    float acc[4][4][4];
#pragma unroll
    for (int mt = 0; mt < 4; mt++)
#pragma unroll
        for (int nt = 0; nt < 4; nt++)
#pragma unroll
            for (int i = 0; i < 4; i++) acc[mt][nt][i] = 0.f;

    auto loadA = [&](int buf, int k0) {
#pragma unroll
        for (int i = 0; i < 2; i++) {
            int c = tid + i * NTHREADS;      // 0..511
            int m = c >> 2, kc = (c & 3) * 4;
            const float* src;
            if (MOE) src = A + (size_t)rows_s[m] * NF + k0 + kc;
            else     src = A + (size_t)(m0blk + m) * NF + k0 + kc;
            CPA16(smem_u32(&As[buf][m][kc]), src);
        }
    };
    auto loadB = [&](int buf, int k0) {
#pragma unroll
        for (int i = 0; i < 2; i++) {
            int c = tid + i * NTHREADS;      // 0..511
            int kr = c >> 5, nc = (c & 31) * 4;
            const float* src = Wp + (size_t)(k0 + kr) * NU + n0blk + nc;
            CPA16(smem_u32(&Bs[buf][kr][nc]), src);
        }
    };

    loadA(0, 0);
    loadB(0, 0);
    asm volatile("cp.async.commit_group;");

    for (int kt = 0; kt < NKITER; kt++) {
        const int cb = kt & 1, nb = (kt + 1) & 1;
        if (kt + 1 < NKITER) { loadA(nb, (kt + 1) * BK); loadB(nb, (kt + 1) * BK); }
        asm volatile("cp.async.commit_group;");
        asm volatile("cp.async.wait_group 1;");
        __syncthreads();

#pragma unroll
        for (int ks = 0; ks < 2; ks++) {
            const int k8 = ks * 8;
            uint32_t a[4][4], b[4][2];
#pragma unroll
            for (int mt = 0; mt < 4; mt++) {
                int mr = wm + mt * 16 + g;
                a[mt][0] = f2tf(As[cb][mr    ][k8 + tig]);
                a[mt][1] = f2tf(As[cb][mr + 8][k8 + tig]);
                a[mt][2] = f2tf(As[cb][mr    ][k8 + tig + 4]);
                a[mt][3] = f2tf(As[cb][mr + 8][k8 + tig + 4]);
            }
#pragma unroll
            for (int nt = 0; nt < 4; nt++) {
                int nc = wn + nt * 8 + g;
                b[nt][0] = f2tf(Bs[cb][k8 + tig    ][nc]);
                b[nt][1] = f2tf(Bs[cb][k8 + tig + 4][nc]);
            }
#pragma unroll
            for (int mt = 0; mt < 4; mt++)
#pragma unroll
                for (int nt = 0; nt < 4; nt++) mma8(acc[mt][nt], a[mt], b[nt]);
        }
        __syncthreads();
    }

    const int cntc = MOE ? (cnt < BM ? cnt : BM) : BM;
#pragma unroll
    for (int mt = 0; mt < 4; mt++) {
#pragma unroll
        for (int nt = 0; nt < 4; nt++) {
            int r0 = wm + mt * 16 + g;
            int r1 = r0 + 8;
            int cg0 = n0blk + wn + nt * 8 + 2 * tig;
            int cg1 = cg0 + 1;
            float bz0 = biasp[cg0], bz1 = biasp[cg1];
            if (MOE) {
                if (r0 < cntc) {
                    int tok = rows_s[r0]; float gt = gate_s[r0];
                    atomicAdd(&C[(size_t)tok * NU + cg0], gt * fmaxf(acc[mt][nt][0] + bz0, 0.f));
                    atomicAdd(&C[(size_t)tok * NU + cg1], gt * fmaxf(acc[mt][nt][1] + bz1, 0.f));
                }
                if (r1 < cntc) {
                    int tok = rows_s[r1]; float gt = gate_s[r1];
                    atomicAdd(&C[(size_t)tok * NU + cg0], gt * fmaxf(acc[mt][nt][2] + bz0, 0.f));
                    atomicAdd(&C[(size_t)tok * NU + cg1], gt * fmaxf(acc[mt][nt][3] + bz1, 0.f));
                }
            } else {
                size_t ro0 = (size_t)(m0blk + r0) * NU;
                size_t ro1 = (size_t)(m0blk + r1) * NU;
                C[ro0 + cg0] = acc[mt][nt][0] + bz0;
                C[ro0 + cg1] = acc[mt][nt][1] + bz1;
                C[ro1 + cg0] = acc[mt][nt][2] + bz0;
                C[ro1 + cg1] = acc[mt][nt][3] + bz1;
            }
        }
    }
}

// ---------------- per-token single-latent attention ----------------
__global__ void attn_kernel() {
    const int b = blockIdx.x;
    const int tid = threadIdx.x;  // 256
    const int warp = tid >> 5, lane = tid & 31;

    __shared__ float sc[NH];
    const float4* q4 = (const float4*)(g_q + (size_t)b * NDM);
    const float4* k4 = (const float4*)(g_k + (size_t)b * NDM);
    const float4* v4 = (const float4*)(g_v + (size_t)b * NDM);
    float4* o4 = (float4*)(g_att + (size_t)b * NDM);

#pragma unroll
    for (int i = 0; i < 2; i++) {
        int h = warp * 2 + i;
        float4 qv = q4[h * 32 + lane];
        float4 kv = k4[h * 32 + lane];
        float s = qv.x * kv.x + qv.y * kv.y + qv.z * kv.z + qv.w * kv.w;
#pragma unroll
        for (int o = 16; o; o >>= 1) s += __shfl_xor_sync(0xffffffffu, s, o);
        if (lane == 0) sc[h] = s * 0.08838834764831845f;  // 1/sqrt(128)
    }
    __syncthreads();

    float mx = sc[0];
#pragma unroll
    for (int h = 1; h < NH; h++) mx = fmaxf(mx, sc[h]);
    float ssum = 0.f;
#pragma unroll
    for (int h = 0; h < NH; h++) ssum += expf(sc[h] - mx);
    float inv = 1.f / ssum;
    // this thread only touches heads (warp) and (warp+8)
    float a0 = expf(sc[warp] - mx) * inv;
    float a1 = expf(sc[warp + 8] - mx) * inv;

    {
        float4 vv = v4[tid];            // head = tid>>5 = warp
        o4[tid] = make_float4(a0 * vv.x, a0 * vv.y, a0 * vv.z, a0 * vv.w);
    }
    {
        float4 vv = v4[tid + 256];      // head = warp + 8
        o4[tid + 256] = make_float4(a1 * vv.x, a1 * vv.y, a1 * vv.z, a1 * vv.w);
    }
}

// ---------------- launcher ----------------
extern "C" void kernel_launch(void* const* d_in, const int* in_sizes, int n_in,
                              void* d_out, int out_size) {
    const float* x  = (const float*)d_in[0];
    const float* rw = (const float*)d_in[1];
    const float* rb = (const float*)d_in[2];
    const float* ew = (const float*)d_in[3];
    const float* eb = (const float*)d_in[4];
    const float* wq = (const float*)d_in[5];
    const float* bq = (const float*)d_in[6];
    const float* wk = (const float*)d_in[7];
    const float* bk = (const float*)d_in[8];
    const float* wv = (const float*)d_in[9];
    const float* bv = (const float*)d_in[10];
    const float* wo = (const float*)d_in[11];
    const float* bo = (const float*)d_in[12];
    float* out = (float*)d_out;

    float *p_moe, *p_q, *p_k, *p_v, *p_att;
    cudaGetSymbolAddress((void**)&p_moe, g_moe);
    cudaGetSymbolAddress((void**)&p_q,   g_q);
    cudaGetSymbolAddress((void**)&p_k,   g_k);
    cudaGetSymbolAddress((void**)&p_v,   g_v);
    cudaGetSymbolAddress((void**)&p_att, g_att);

    zero_kernel<<<2048, 256>>>();
    router_kernel<<<NB, 128>>>(x, rw, rb);

    // sparse MoE: grid z = expert, y = token-tile (overprovisioned, early exit)
    gemm_kernel<true><<<dim3(NU / BN, NB / BM, NE), NTHREADS>>>(x, ew, eb, p_moe);

    gemm_kernel<false><<<dim3(NDM / BN, NB / BM), NTHREADS>>>(p_moe, wq, bq, p_q);
    gemm_kernel<false><<<dim3(NDM / BN, NB / BM), NTHREADS>>>(p_moe, wk, bk, p_k);
    gemm_kernel<false><<<dim3(NDM / BN, NB / BM), NTHREADS>>>(p_moe, wv, bv, p_v);

    attn_kernel<<<NB, 256>>>();

    gemm_kernel<false><<<dim3(NDM / BN, NB / BM), NTHREADS>>>(p_att, wo, bo, out);
}

// round 6
// speedup vs baseline: 1.7040x; 1.7040x over previous
#include <cuda_runtime.h>
#include <cuda_fp16.h>
#include <cstdint>

// ---------------- problem dims ----------------
#define NB 8192
#define NF 2048
#define NE 16
#define NU 2048
#define NDM 2048
#define NH 16

// ---------------- device scratch (static, no allocations) ----------------
__device__ __half g_xh  [(size_t)NB * NF];
__device__ __half g_moeh[(size_t)NB * NU];
__device__ float  g_p0  [(size_t)NB * NU];
__device__ float  g_p1  [(size_t)NB * NU];
__device__ float  g_q   [(size_t)NB * NDM];
__device__ float  g_k   [(size_t)NB * NDM];
__device__ float  g_v   [(size_t)NB * NDM];
__device__ __half g_atth[(size_t)NB * NDM];
__device__ __half g_ewt [(size_t)NE * NU * NF];
__device__ __half g_wtq [(size_t)NDM * NU];
__device__ __half g_wtk [(size_t)NDM * NU];
__device__ __half g_wtv [(size_t)NDM * NU];
__device__ __half g_wto [(size_t)NDM * NDM];
__device__ int    g_counts[NE];
__device__ int    g_rows [NE * NB];
__device__ float  g_gates[NE * NB];
__device__ unsigned char g_slots[NE * NB];

// ---------------- helpers ----------------
__device__ __forceinline__ uint32_t smem_u32(const void* p) {
    return (uint32_t)__cvta_generic_to_shared(p);
}
#define CPA16(dst, src) \
    asm volatile("cp.async.cg.shared.global [%0], [%1], 16;" :: "r"(dst), "l"(src))

__device__ __forceinline__ void mma16(float* c, const uint32_t* a, const uint32_t* b) {
    asm volatile(
        "mma.sync.aligned.m16n8k16.row.col.f32.f16.f16.f32 "
        "{%0,%1,%2,%3},{%4,%5,%6,%7},{%8,%9},{%0,%1,%2,%3};"
        : "+f"(c[0]), "+f"(c[1]), "+f"(c[2]), "+f"(c[3])
        : "r"(a[0]), "r"(a[1]), "r"(a[2]), "r"(a[3]), "r"(b[0]), "r"(b[1]));
}

// ---------------- prep kernels ----------------
__global__ void prep_kernel() {
    if (threadIdx.x < NE) g_counts[threadIdx.x] = 0;
}

// fp32 -> fp16 convert (vectorized)
__global__ void cvt_kernel(const float* __restrict__ src, __half* __restrict__ dst, size_t n4) {
    const float4* s = (const float4*)src;
    uint2* d = (uint2*)dst;
    for (size_t i = (size_t)blockIdx.x * blockDim.x + threadIdx.x; i < n4;
         i += (size_t)gridDim.x * blockDim.x) {
        float4 v = s[i];
        __half2 lo = __floats2half2_rn(v.x, v.y);
        __half2 hi = __floats2half2_rn(v.z, v.w);
        uint2 o;
        o.x = *(uint32_t*)&lo;
        o.y = *(uint32_t*)&hi;
        d[i] = o;
    }
}

// combine MoE partial slots -> fp16 A operand for QKV GEMMs
__global__ void combine_kernel() {
    size_t n = (size_t)NB * NU / 4;
    const float4* a = (const float4*)g_p0;
    const float4* b = (const float4*)g_p1;
    uint2* d = (uint2*)g_moeh;
    for (size_t i = (size_t)blockIdx.x * blockDim.x + threadIdx.x; i < n;
         i += (size_t)gridDim.x * blockDim.x) {
        float4 u = a[i], w = b[i];
        __half2 lo = __floats2half2_rn(u.x + w.x, u.y + w.y);
        __half2 hi = __floats2half2_rn(u.z + w.z, u.w + w.w);
        uint2 o;
        o.x = *(uint32_t*)&lo;
        o.y = *(uint32_t*)&hi;
        d[i] = o;
    }
}

// transpose src[b][r][c] (fp32) -> dst[b][c][r] (fp16)
__global__ void transpose_kernel(const float* __restrict__ src, __half* __restrict__ dst,
                                 int R, int C) {
    __shared__ float t[32][33];
    const int b = blockIdx.z;
    const float* s = src + (size_t)b * R * C;
    __half* d = dst + (size_t)b * R * C;
    const int r0 = blockIdx.y * 32, c0 = blockIdx.x * 32;
    const int x = threadIdx.x, y = threadIdx.y;  // 32 x 8
#pragma unroll
    for (int i = 0; i < 32; i += 8)
        t[y + i][x] = s[(size_t)(r0 + y + i) * C + c0 + x];
    __syncthreads();
#pragma unroll
    for (int i = 0; i < 32; i += 8)
        d[(size_t)(c0 + y + i) * R + r0 + x] = __float2half_rn(t[x][y + i]);
}

// ---------------- router: fp32 logits, softmax, top-2, token lists ----------------
__global__ void router_kernel(const float* __restrict__ x,
                              const float* __restrict__ rw,
                              const float* __restrict__ rb) {
    const int b = blockIdx.x;
    const int tid = threadIdx.x;  // 128 threads
    float part[NE];
#pragma unroll
    for (int e = 0; e < NE; e++) part[e] = 0.f;

    const float* xr = x + (size_t)b * NF;
    for (int f = tid; f < NF; f += 128) {
        float xv = xr[f];
        const float4* w4 = (const float4*)(rw + (size_t)f * NE);
#pragma unroll
        for (int e4 = 0; e4 < 4; e4++) {
            float4 w = w4[e4];
            part[e4 * 4 + 0] += xv * w.x;
            part[e4 * 4 + 1] += xv * w.y;
            part[e4 * 4 + 2] += xv * w.z;
            part[e4 * 4 + 3] += xv * w.w;
        }
    }

    __shared__ float red[NE][128];
#pragma unroll
    for (int e = 0; e < NE; e++) red[e][tid] = part[e];
    __syncthreads();

    __shared__ float lg[NE];
    if (tid < NE) {
        float s = 0.f;
        for (int j = 0; j < 128; j++) s += red[tid][j];
        lg[tid] = s + rb[tid];
    }
    __syncthreads();

    if (tid == 0) {
        float mx = lg[0];
#pragma unroll
        for (int e = 1; e < NE; e++) mx = fmaxf(mx, lg[e]);
        float p[NE];
        float s = 0.f;
#pragma unroll
        for (int e = 0; e < NE; e++) { p[e] = expf(lg[e] - mx); s += p[e]; }
        int e0 = 0; float b0 = p[0];
#pragma unroll
        for (int e = 1; e < NE; e++) if (p[e] > b0) { b0 = p[e]; e0 = e; }
        int e1 = -1; float b1 = -1.f;
#pragma unroll
        for (int e = 0; e < NE; e++)
            if (e != e0 && p[e] > b1) { b1 = p[e]; e1 = e; }
        float inv = 1.f / s;
        int pos = atomicAdd(&g_counts[e0], 1);
        g_rows [e0 * NB + pos] = b;
        g_gates[e0 * NB + pos] = b0 * inv;
        g_slots[e0 * NB + pos] = 0;
        pos = atomicAdd(&g_counts[e1], 1);
        g_rows [e1 * NB + pos] = b;
        g_gates[e1 * NB + pos] = b1 * inv;
        g_slots[e1 * NB + pos] = 1;
    }
}

// ---------------- fp16 GEMM: 128x128x32 tiles, cp.async double buffer ----------------
#define BM 128
#define BN 128
#define BK 32                      // halves per k-stage
#define LDA (BK + 8)               // 40 halves = 80B rows: conflict-free
#define LDB (BK + 8)
#define NTHREADS 256
#define NKITER (NF / BK)           // 64

// MOE=true : A rows gathered via g_rows; gate*relu(acc+bias) -> g_p0/g_p1 by slot
// MOE=false: plain C = A@Bt^T + bias (fp32 out)
template <bool MOE>
__global__ __launch_bounds__(NTHREADS) void gemm_kernel(
    const __half* __restrict__ A, const __half* __restrict__ Bt,
    const float* __restrict__ bias, float* __restrict__ C) {
    __shared__ __half As[2][BM][LDA];
    __shared__ __half Bs[2][BN][LDB];
    __shared__ int rows_s[BM];
    __shared__ float gate_s[BM];
    __shared__ int slot_s[BM];

    const int tid = threadIdx.x;
    const int n0blk = blockIdx.x * BN;
    const int m0blk = blockIdx.y * BM;

    int cnt = BM;
    const __half* Bp = Bt;
    const float* biasp = bias;
    if (MOE) {
        const int e = blockIdx.z;
        const int ce = g_counts[e];
        cnt = ce - m0blk;
        if (cnt <= 0) return;
        if (cnt > BM) cnt = BM;
        Bp = Bt + (size_t)e * NU * NF;
        biasp = bias + e * NU;
        if (tid < BM) {
            bool v = tid < cnt;
            rows_s[tid] = v ? g_rows [e * NB + m0blk + tid] : 0;
            gate_s[tid] = v ? g_gates[e * NB + m0blk + tid] : 0.f;
            slot_s[tid] = v ? (int)g_slots[e * NB + m0blk + tid] : 0;
        }
        __syncthreads();
    }

    const int lane = tid & 31, warp = tid >> 5;
    const int wm = (warp >> 2) * 64;
    const int wn = (warp & 3) * 32;
    const int g = lane >> 2, tig = lane & 3;

    float acc[4][4][4];
#pragma unroll
    for (int mt = 0; mt < 4; mt++)
#pragma unroll
        for (int nt = 0; nt < 4; nt++)
#pragma unroll
            for (int i = 0; i < 4; i++) acc[mt][nt][i] = 0.f;

    // per stage: 128 rows x 32 halves = 64B/row = 4 x 16B chunks; 512 chunks
    auto loadA = [&](int buf, int k0) {
#pragma unroll
        for (int i = 0; i < 2; i++) {
            int c = tid + i * NTHREADS;     // 0..511
            int m = c >> 2, hc = (c & 3) * 8;
            const __half* src;
            if (MOE) src = A + (size_t)rows_s[m] * NF + k0 + hc;
            else     src = A + (size_t)(m0blk + m) * NF + k0 + hc;
            CPA16(smem_u32(&As[buf][m][hc]), src);
        }
    };
    auto loadB = [&](int buf, int k0) {
#pragma unroll
        for (int i = 0; i < 2; i++) {
            int c = tid + i * NTHREADS;
            int n = c >> 2, hc = (c & 3) * 8;
            CPA16(smem_u32(&Bs[buf][n][hc]), Bp + (size_t)(n0blk + n) * NF + k0 + hc);
        }
    };

    loadA(0, 0);
    loadB(0, 0);
    asm volatile("cp.async.commit_group;");

    for (int kt = 0; kt < NKITER; kt++) {
        const int cb = kt & 1, nb = (kt + 1) & 1;
        if (kt + 1 < NKITER) { loadA(nb, (kt + 1) * BK); loadB(nb, (kt + 1) * BK); }
        asm volatile("cp.async.commit_group;");
        asm volatile("cp.async.wait_group 1;");
        __syncthreads();

#pragma unroll
        for (int ks = 0; ks < 2; ks++) {
            const int k16 = ks * 16;
            uint32_t a[4][4], b[4][2];
#pragma unroll
            for (int mt = 0; mt < 4; mt++) {
                int mr = wm + mt * 16 + g;
                a[mt][0] = *(const uint32_t*)&As[cb][mr    ][k16 + 2 * tig];
                a[mt][1] = *(const uint32_t*)&As[cb][mr + 8][k16 + 2 * tig];
                a[mt][2] = *(const uint32_t*)&As[cb][mr    ][k16 + 8 + 2 * tig];
                a[mt][3] = *(const uint32_t*)&As[cb][mr + 8][k16 + 8 + 2 * tig];
            }
#pragma unroll
            for (int nt = 0; nt < 4; nt++) {
                int nc = wn + nt * 8 + g;
                b[nt][0] = *(const uint32_t*)&Bs[cb][nc][k16 + 2 * tig];
                b[nt][1] = *(const uint32_t*)&Bs[cb][nc][k16 + 8 + 2 * tig];
            }
#pragma unroll
            for (int mt = 0; mt < 4; mt++)
#pragma unroll
                for (int nt = 0; nt < 4; nt++) mma16(acc[mt][nt], a[mt], b[nt]);
        }
        __syncthreads();
    }

#pragma unroll
    for (int mt = 0; mt < 4; mt++) {
#pragma unroll
        for (int nt = 0; nt < 4; nt++) {
            int r0 = wm + mt * 16 + g;
            int r1 = r0 + 8;
            int cg0 = n0blk + wn + nt * 8 + 2 * tig;
            int cg1 = cg0 + 1;
            float bz0 = biasp[cg0], bz1 = biasp[cg1];
            if (MOE) {
                if (r0 < cnt) {
                    int tok = rows_s[r0]; float gt = gate_s[r0];
                    float* dst = (slot_s[r0] ? g_p1 : g_p0) + (size_t)tok * NU;
                    dst[cg0] = gt * fmaxf(acc[mt][nt][0] + bz0, 0.f);
                    dst[cg1] = gt * fmaxf(acc[mt][nt][1] + bz1, 0.f);
                }
                if (r1 < cnt) {
                    int tok = rows_s[r1]; float gt = gate_s[r1];
                    float* dst = (slot_s[r1] ? g_p1 : g_p0) + (size_t)tok * NU;
                    dst[cg0] = gt * fmaxf(acc[mt][nt][2] + bz0, 0.f);
                    dst[cg1] = gt * fmaxf(acc[mt][nt][3] + bz1, 0.f);
                }
            } else {
                size_t ro0 = (size_t)(m0blk + r0) * NU;
                size_t ro1 = (size_t)(m0blk + r1) * NU;
                C[ro0 + cg0] = acc[mt][nt][0] + bz0;
                C[ro0 + cg1] = acc[mt][nt][1] + bz1;
                C[ro1 + cg0] = acc[mt][nt][2] + bz0;
                C[ro1 + cg1] = acc[mt][nt][3] + bz1;
            }
        }
    }
}

// ---------------- per-token single-latent attention (fp32 math, fp16 out) ----------
__global__ void attn_kernel() {
    const int b = blockIdx.x;
    const int tid = threadIdx.x;  // 256
    const int warp = tid >> 5, lane = tid & 31;

    __shared__ float sc[NH];
    const float4* q4 = (const float4*)(g_q + (size_t)b * NDM);
    const float4* k4 = (const float4*)(g_k + (size_t)b * NDM);
    const float4* v4 = (const float4*)(g_v + (size_t)b * NDM);
    uint2* o4 = (uint2*)(g_atth + (size_t)b * NDM);

#pragma unroll
    for (int i = 0; i < 2; i++) {
        int h = warp * 2 + i;
        float4 qv = q4[h * 32 + lane];
        float4 kv = k4[h * 32 + lane];
        float s = qv.x * kv.x + qv.y * kv.y + qv.z * kv.z + qv.w * kv.w;
#pragma unroll
        for (int o = 16; o; o >>= 1) s += __shfl_xor_sync(0xffffffffu, s, o);
        if (lane == 0) sc[h] = s * 0.08838834764831845f;  // 1/sqrt(128)
    }
    __syncthreads();

    float mx = sc[0];
#pragma unroll
    for (int h = 1; h < NH; h++) mx = fmaxf(mx, sc[h]);
    float ssum = 0.f;
#pragma unroll
    for (int h = 0; h < NH; h++) ssum += expf(sc[h] - mx);
    float inv = 1.f / ssum;
    float a0 = expf(sc[warp] - mx) * inv;
    float a1 = expf(sc[warp + 8] - mx) * inv;

    {
        float4 vv = v4[tid];
        __half2 lo = __floats2half2_rn(a0 * vv.x, a0 * vv.y);
        __half2 hi = __floats2half2_rn(a0 * vv.z, a0 * vv.w);
        uint2 o; o.x = *(uint32_t*)&lo; o.y = *(uint32_t*)&hi;
        o4[tid] = o;
    }
    {
        float4 vv = v4[tid + 256];
        __half2 lo = __floats2half2_rn(a1 * vv.x, a1 * vv.y);
        __half2 hi = __floats2half2_rn(a1 * vv.z, a1 * vv.w);
        uint2 o; o.x = *(uint32_t*)&lo; o.y = *(uint32_t*)&hi;
        o4[tid + 256] = o;
    }
}

// ---------------- launcher ----------------
extern "C" void kernel_launch(void* const* d_in, const int* in_sizes, int n_in,
                              void* d_out, int out_size) {
    const float* x  = (const float*)d_in[0];
    const float* rw = (const float*)d_in[1];
    const float* rb = (const float*)d_in[2];
    const float* ew = (const float*)d_in[3];
    const float* eb = (const float*)d_in[4];
    const float* wq = (const float*)d_in[5];
    const float* bq = (const float*)d_in[6];
    const float* wk = (const float*)d_in[7];
    const float* bk = (const float*)d_in[8];
    const float* wv = (const float*)d_in[9];
    const float* bv = (const float*)d_in[10];
    const float* wo = (const float*)d_in[11];
    const float* bo = (const float*)d_in[12];
    float* out = (float*)d_out;

    __half *p_xh, *p_moeh, *p_atth, *p_ewt, *p_wtq, *p_wtk, *p_wtv, *p_wto;
    float *p_q, *p_k, *p_v;
    cudaGetSymbolAddress((void**)&p_xh,   g_xh);
    cudaGetSymbolAddress((void**)&p_moeh, g_moeh);
    cudaGetSymbolAddress((void**)&p_atth, g_atth);
    cudaGetSymbolAddress((void**)&p_ewt,  g_ewt);
    cudaGetSymbolAddress((void**)&p_wtq,  g_wtq);
    cudaGetSymbolAddress((void**)&p_wtk,  g_wtk);
    cudaGetSymbolAddress((void**)&p_wtv,  g_wtv);
    cudaGetSymbolAddress((void**)&p_wto,  g_wto);
    cudaGetSymbolAddress((void**)&p_q,    g_q);
    cudaGetSymbolAddress((void**)&p_k,    g_k);
    cudaGetSymbolAddress((void**)&p_v,    g_v);

    prep_kernel<<<1, 32>>>();
    router_kernel<<<NB, 128>>>(x, rw, rb);

    // operand conversion / weight transposes (fp32 -> fp16 K-major)
    cvt_kernel<<<2048, 256>>>(x, p_xh, (size_t)NB * NF / 4);
    transpose_kernel<<<dim3(NU / 32, NF / 32, NE), dim3(32, 8)>>>(ew, p_ewt, NF, NU);
    transpose_kernel<<<dim3(NDM / 32, NU / 32, 1), dim3(32, 8)>>>(wq, p_wtq, NU, NDM);
    transpose_kernel<<<dim3(NDM / 32, NU / 32, 1), dim3(32, 8)>>>(wk, p_wtk, NU, NDM);
    transpose_kernel<<<dim3(NDM / 32, NU / 32, 1), dim3(32, 8)>>>(wv, p_wtv, NU, NDM);
    transpose_kernel<<<dim3(NDM / 32, NDM / 32, 1), dim3(32, 8)>>>(wo, p_wto, NDM, NDM);

    // sparse MoE (z = expert, y = token-tile, overprovisioned with early exit)
    gemm_kernel<true><<<dim3(NU / BN, NB / BM, NE), NTHREADS>>>(p_xh, p_ewt, eb, nullptr);
    combine_kernel<<<2048, 256>>>();

    gemm_kernel<false><<<dim3(NDM / BN, NB / BM), NTHREADS>>>(p_moeh, p_wtq, bq, p_q);
    gemm_kernel<false><<<dim3(NDM / BN, NB / BM), NTHREADS>>>(p_moeh, p_wtk, bk, p_k);
    gemm_kernel<false><<<dim3(NDM / BN, NB / BM), NTHREADS>>>(p_moeh, p_wtv, bv, p_v);

    attn_kernel<<<NB, 256>>>();

    gemm_kernel<false><<<dim3(NDM / BN, NB / BM), NTHREADS>>>(p_atth, p_wto, bo, out);
}

// round 7
// speedup vs baseline: 2.0294x; 1.1909x over previous
#include <cuda_runtime.h>
#include <cuda_fp16.h>
#include <cstdint>

// ---------------- problem dims ----------------
#define NB 8192
#define NF 2048
#define NE 16
#define NU 2048
#define NDM 2048
#define NH 16

// ---------------- device scratch (static, no allocations) ----------------
__device__ __half g_xh  [(size_t)NB * NF];
__device__ __half g_moeh[(size_t)NB * NU];
__device__ float  g_p0  [(size_t)NB * NU];
__device__ float  g_p1  [(size_t)NB * NU];
__device__ float  g_q   [(size_t)NB * NDM];
__device__ float  g_k   [(size_t)NB * NDM];
__device__ float  g_v   [(size_t)NB * NDM];
__device__ __half g_atth[(size_t)NB * NDM];
__device__ __half g_ewh [(size_t)NE * NF * NU];   // fp16 expert weights, native [E][F][U]
__device__ __half g_wqh [(size_t)NU * NDM];       // native [U][D]
__device__ __half g_wkh [(size_t)NU * NDM];
__device__ __half g_wvh [(size_t)NU * NDM];
__device__ __half g_woh [(size_t)NDM * NDM];
__device__ int    g_counts[NE];
__device__ int    g_rows [NE * NB];
__device__ float  g_gates[NE * NB];
__device__ unsigned char g_slots[NE * NB];

// ---------------- helpers ----------------
__device__ __forceinline__ uint32_t smem_u32(const void* p) {
    return (uint32_t)__cvta_generic_to_shared(p);
}
#define CPA16(dst, src) \
    asm volatile("cp.async.cg.shared.global [%0], [%1], 16;" :: "r"(dst), "l"(src))

__device__ __forceinline__ void mma16(float* c, const uint32_t* a, const uint32_t* b) {
    asm volatile(
        "mma.sync.aligned.m16n8k16.row.col.f32.f16.f16.f32 "
        "{%0,%1,%2,%3},{%4,%5,%6,%7},{%8,%9},{%0,%1,%2,%3};"
        : "+f"(c[0]), "+f"(c[1]), "+f"(c[2]), "+f"(c[3])
        : "r"(a[0]), "r"(a[1]), "r"(a[2]), "r"(a[3]), "r"(b[0]), "r"(b[1]));
}

#define LDSM4(r, addr) \
    asm volatile("ldmatrix.sync.aligned.m8n8.x4.shared.b16 {%0,%1,%2,%3}, [%4];" \
                 : "=r"((r)[0]), "=r"((r)[1]), "=r"((r)[2]), "=r"((r)[3]) : "r"(addr))
#define LDSM4T(r, addr) \
    asm volatile("ldmatrix.sync.aligned.m8n8.x4.trans.shared.b16 {%0,%1,%2,%3}, [%4];" \
                 : "=r"((r)[0]), "=r"((r)[1]), "=r"((r)[2]), "=r"((r)[3]) : "r"(addr))

// ---------------- prep kernels ----------------
__global__ void prep_kernel() {
    if (threadIdx.x < NE) g_counts[threadIdx.x] = 0;
}

// fp32 -> fp16 streaming convert (no transpose needed: GEMM reads B k-major)
__global__ void cvt_kernel(const float* __restrict__ src, __half* __restrict__ dst, size_t n4) {
    const float4* s = (const float4*)src;
    uint2* d = (uint2*)dst;
    for (size_t i = (size_t)blockIdx.x * blockDim.x + threadIdx.x; i < n4;
         i += (size_t)gridDim.x * blockDim.x) {
        float4 v = s[i];
        __half2 lo = __floats2half2_rn(v.x, v.y);
        __half2 hi = __floats2half2_rn(v.z, v.w);
        uint2 o;
        o.x = *(uint32_t*)&lo;
        o.y = *(uint32_t*)&hi;
        d[i] = o;
    }
}

// combine MoE partial slots -> fp16 A operand for QKV GEMMs
__global__ void combine_kernel() {
    size_t n = (size_t)NB * NU / 4;
    const float4* a = (const float4*)g_p0;
    const float4* b = (const float4*)g_p1;
    uint2* d = (uint2*)g_moeh;
    for (size_t i = (size_t)blockIdx.x * blockDim.x + threadIdx.x; i < n;
         i += (size_t)gridDim.x * blockDim.x) {
        float4 u = a[i], w = b[i];
        __half2 lo = __floats2half2_rn(u.x + w.x, u.y + w.y);
        __half2 hi = __floats2half2_rn(u.z + w.z, u.w + w.w);
        uint2 o;
        o.x = *(uint32_t*)&lo;
        o.y = *(uint32_t*)&hi;
        d[i] = o;
    }
}

// ---------------- router: fp32 logits, softmax, top-2 + fused x->fp16 ----------------
__global__ void router_kernel(const float* __restrict__ x,
                              const float* __restrict__ rw,
                              const float* __restrict__ rb) {
    const int b = blockIdx.x;
    const int tid = threadIdx.x;  // 128 threads
    float part[NE];
#pragma unroll
    for (int e = 0; e < NE; e++) part[e] = 0.f;

    const float* xr = x + (size_t)b * NF;
    __half* xh = g_xh + (size_t)b * NF;
    for (int f = tid; f < NF; f += 128) {
        float xv = xr[f];
        xh[f] = __float2half_rn(xv);          // fused fp16 conversion
        const float4* w4 = (const float4*)(rw + (size_t)f * NE);
#pragma unroll
        for (int e4 = 0; e4 < 4; e4++) {
            float4 w = w4[e4];
            part[e4 * 4 + 0] += xv * w.x;
            part[e4 * 4 + 1] += xv * w.y;
            part[e4 * 4 + 2] += xv * w.z;
            part[e4 * 4 + 3] += xv * w.w;
        }
    }

    __shared__ float red[NE][128];
#pragma unroll
    for (int e = 0; e < NE; e++) red[e][tid] = part[e];
    __syncthreads();

    __shared__ float lg[NE];
    if (tid < NE) {
        float s = 0.f;
        for (int j = 0; j < 128; j++) s += red[tid][j];
        lg[tid] = s + rb[tid];
    }
    __syncthreads();

    if (tid == 0) {
        float mx = lg[0];
#pragma unroll
        for (int e = 1; e < NE; e++) mx = fmaxf(mx, lg[e]);
        float p[NE];
        float s = 0.f;
#pragma unroll
        for (int e = 0; e < NE; e++) { p[e] = expf(lg[e] - mx); s += p[e]; }
        int e0 = 0; float b0 = p[0];
#pragma unroll
        for (int e = 1; e < NE; e++) if (p[e] > b0) { b0 = p[e]; e0 = e; }
        int e1 = -1; float b1 = -1.f;
#pragma unroll
        for (int e = 0; e < NE; e++)
            if (e != e0 && p[e] > b1) { b1 = p[e]; e1 = e; }
        float inv = 1.f / s;
        int pos = atomicAdd(&g_counts[e0], 1);
        g_rows [e0 * NB + pos] = b;
        g_gates[e0 * NB + pos] = b0 * inv;
        g_slots[e0 * NB + pos] = 0;
        pos = atomicAdd(&g_counts[e1], 1);
        g_rows [e1 * NB + pos] = b;
        g_gates[e1 * NB + pos] = b1 * inv;
        g_slots[e1 * NB + pos] = 1;
    }
}

// ---------------- fp16 GEMM: 128x128x32 tiles, ldmatrix + cp.async double buffer ----
// A: [*, NF/NU] fp16 row-major (M-major). B: fp16 [K][N] native layout (k-major rows).
#define BM 128
#define BN 128
#define BK 32
#define LDA 40        // halves/row: 80B stride -> LDSM 8-row phases all distinct
#define LDB2 136      // halves/row: 272B stride -> LDSM 8-row phases all distinct
#define NTHREADS 256
#define NKITER (NF / BK)  // 64

template <bool MOE>
__global__ __launch_bounds__(NTHREADS) void gemm_kernel(
    const __half* __restrict__ A, const __half* __restrict__ B,
    const float* __restrict__ bias, float* __restrict__ C) {
    __shared__ __half As[2][BM][LDA];
    __shared__ __half Bs[2][BK][LDB2];
    __shared__ int rows_s[BM];
    __shared__ float gate_s[BM];
    __shared__ int slot_s[BM];

    const int tid = threadIdx.x;
    const int n0blk = blockIdx.x * BN;
    const int m0blk = blockIdx.y * BM;

    int cnt = BM;
    const __half* Bp = B;
    const float* biasp = bias;
    if (MOE) {
        const int e = blockIdx.z;
        const int ce = g_counts[e];
        cnt = ce - m0blk;
        if (cnt <= 0) return;
        if (cnt > BM) cnt = BM;
        Bp = B + (size_t)e * NF * NU;
        biasp = bias + e * NU;
        if (tid < BM) {
            bool v = tid < cnt;
            rows_s[tid] = v ? g_rows [e * NB + m0blk + tid] : 0;
            gate_s[tid] = v ? g_gates[e * NB + m0blk + tid] : 0.f;
            slot_s[tid] = v ? (int)g_slots[e * NB + m0blk + tid] : 0;
        }
        __syncthreads();
    }

    const int lane = tid & 31, warp = tid >> 5;
    const int wm = (warp >> 2) * 64;     // 2 warp-rows x 64
    const int wn = (warp & 3) * 32;      // 4 warp-cols x 32
    const int g = lane >> 2, tig = lane & 3;

    // per-thread ldmatrix row/col selectors
    const int l15 = lane & 15;
    const int lhi = (lane >> 4) * 8;
    const uint32_t baseA = smem_u32(&As[0][0][0]);
    const uint32_t baseB = smem_u32(&Bs[0][0][0]);
    // A: addr(cb, mt, ks) = baseA + cb*szA + ((wm + mt*16 + l15)*LDA + ks*16 + lhi)*2
    const uint32_t aoff = ((wm + l15) * LDA + lhi) * 2;
    // B: addr(cb, ntp, ks) = baseB + cb*szB + ((ks*16 + l15)*LDB2 + wn + ntp*16 + lhi)*2
    const uint32_t boff = (l15 * LDB2 + wn + lhi) * 2;
    const uint32_t szA = BM * LDA * 2;
    const uint32_t szB = BK * LDB2 * 2;

    float acc[4][4][4];
#pragma unroll
    for (int mt = 0; mt < 4; mt++)
#pragma unroll
        for (int nt = 0; nt < 4; nt++)
#pragma unroll
            for (int i = 0; i < 4; i++) acc[mt][nt][i] = 0.f;

    // A stage: 128 rows x 64B; 512 x 16B chunks. B stage: 32 rows x 256B; 512 chunks.
    auto loadA = [&](int buf, int k0) {
#pragma unroll
        for (int i = 0; i < 2; i++) {
            int c = tid + i * NTHREADS;
            int m = c >> 2, hc = (c & 3) * 8;
            const __half* src;
            if (MOE) src = A + (size_t)rows_s[m] * NF + k0 + hc;
            else     src = A + (size_t)(m0blk + m) * NF + k0 + hc;
            CPA16(smem_u32(&As[buf][m][hc]), src);
        }
    };
    auto loadB = [&](int buf, int k0) {
#pragma unroll
        for (int i = 0; i < 2; i++) {
            int c = tid + i * NTHREADS;
            int kr = c >> 4, nc = (c & 15) * 8;
            CPA16(smem_u32(&Bs[buf][kr][nc]), Bp + (size_t)(k0 + kr) * NU + n0blk + nc);
        }
    };

    loadA(0, 0);
    loadB(0, 0);
    asm volatile("cp.async.commit_group;");

    for (int kt = 0; kt < NKITER; kt++) {
        const int cb = kt & 1, nb = (kt + 1) & 1;
        if (kt + 1 < NKITER) { loadA(nb, (kt + 1) * BK); loadB(nb, (kt + 1) * BK); }
        asm volatile("cp.async.commit_group;");
        asm volatile("cp.async.wait_group 1;");
        __syncthreads();

        const uint32_t abase = baseA + cb * szA + aoff;
        const uint32_t bbase = baseB + cb * szB + boff;
#pragma unroll
        for (int ks = 0; ks < 2; ks++) {
            uint32_t a[4][4], b[2][4];
#pragma unroll
            for (int mt = 0; mt < 4; mt++)
                LDSM4(a[mt], abase + (mt * 16 * LDA + ks * 16) * 2);
#pragma unroll
            for (int ntp = 0; ntp < 2; ntp++)
                LDSM4T(b[ntp], bbase + (ks * 16 * LDB2 + ntp * 16) * 2);
#pragma unroll
            for (int mt = 0; mt < 4; mt++)
#pragma unroll
                for (int nt = 0; nt < 4; nt++)
                    mma16(acc[mt][nt], a[mt], &b[nt >> 1][(nt & 1) * 2]);
        }
        __syncthreads();
    }

#pragma unroll
    for (int mt = 0; mt < 4; mt++) {
#pragma unroll
        for (int nt = 0; nt < 4; nt++) {
            int r0 = wm + mt * 16 + g;
            int r1 = r0 + 8;
            int cg0 = n0blk + wn + nt * 8 + 2 * tig;
            int cg1 = cg0 + 1;
            float bz0 = biasp[cg0], bz1 = biasp[cg1];
            if (MOE) {
                if (r0 < cnt) {
                    int tok = rows_s[r0]; float gt = gate_s[r0];
                    float* dst = (slot_s[r0] ? g_p1 : g_p0) + (size_t)tok * NU;
                    dst[cg0] = gt * fmaxf(acc[mt][nt][0] + bz0, 0.f);
                    dst[cg1] = gt * fmaxf(acc[mt][nt][1] + bz1, 0.f);
                }
                if (r1 < cnt) {
                    int tok = rows_s[r1]; float gt = gate_s[r1];
                    float* dst = (slot_s[r1] ? g_p1 : g_p0) + (size_t)tok * NU;
                    dst[cg0] = gt * fmaxf(acc[mt][nt][2] + bz0, 0.f);
                    dst[cg1] = gt * fmaxf(acc[mt][nt][3] + bz1, 0.f);
                }
            } else {
                size_t ro0 = (size_t)(m0blk + r0) * NU;
                size_t ro1 = (size_t)(m0blk + r1) * NU;
                C[ro0 + cg0] = acc[mt][nt][0] + bz0;
                C[ro0 + cg1] = acc[mt][nt][1] + bz1;
                C[ro1 + cg0] = acc[mt][nt][2] + bz0;
                C[ro1 + cg1] = acc[mt][nt][3] + bz1;
            }
        }
    }
}

// ---------------- per-token single-latent attention (fp32 math, fp16 out) ----------
__global__ void attn_kernel() {
    const int b = blockIdx.x;
    const int tid = threadIdx.x;  // 256
    const int warp = tid >> 5, lane = tid & 31;

    __shared__ float sc[NH];
    const float4* q4 = (const float4*)(g_q + (size_t)b * NDM);
    const float4* k4 = (const float4*)(g_k + (size_t)b * NDM);
    const float4* v4 = (const float4*)(g_v + (size_t)b * NDM);
    uint2* o4 = (uint2*)(g_atth + (size_t)b * NDM);

#pragma unroll
    for (int i = 0; i < 2; i++) {
        int h = warp * 2 + i;
        float4 qv = q4[h * 32 + lane];
        float4 kv = k4[h * 32 + lane];
        float s = qv.x * kv.x + qv.y * kv.y + qv.z * kv.z + qv.w * kv.w;
#pragma unroll
        for (int o = 16; o; o >>= 1) s += __shfl_xor_sync(0xffffffffu, s, o);
        if (lane == 0) sc[h] = s * 0.08838834764831845f;  // 1/sqrt(128)
    }
    __syncthreads();

    float mx = sc[0];
#pragma unroll
    for (int h = 1; h < NH; h++) mx = fmaxf(mx, sc[h]);
    float ssum = 0.f;
#pragma unroll
    for (int h = 0; h < NH; h++) ssum += expf(sc[h] - mx);
    float inv = 1.f / ssum;
    float a0 = expf(sc[warp] - mx) * inv;
    float a1 = expf(sc[warp + 8] - mx) * inv;

    {
        float4 vv = v4[tid];
        __half2 lo = __floats2half2_rn(a0 * vv.x, a0 * vv.y);
        __half2 hi = __floats2half2_rn(a0 * vv.z, a0 * vv.w);
        uint2 o; o.x = *(uint32_t*)&lo; o.y = *(uint32_t*)&hi;
        o4[tid] = o;
    }
    {
        float4 vv = v4[tid + 256];
        __half2 lo = __floats2half2_rn(a1 * vv.x, a1 * vv.y);
        __half2 hi = __floats2half2_rn(a1 * vv.z, a1 * vv.w);
        uint2 o; o.x = *(uint32_t*)&lo; o.y = *(uint32_t*)&hi;
        o4[tid + 256] = o;
    }
}

// ---------------- launcher ----------------
extern "C" void kernel_launch(void* const* d_in, const int* in_sizes, int n_in,
                              void* d_out, int out_size) {
    const float* x  = (const float*)d_in[0];
    const float* rw = (const float*)d_in[1];
    const float* rb = (const float*)d_in[2];
    const float* ew = (const float*)d_in[3];
    const float* eb = (const float*)d_in[4];
    const float* wq = (const float*)d_in[5];
    const float* bq = (const float*)d_in[6];
    const float* wk = (const float*)d_in[7];
    const float* bk = (const float*)d_in[8];
    const float* wv = (const float*)d_in[9];
    const float* bv = (const float*)d_in[10];
    const float* wo = (const float*)d_in[11];
    const float* bo = (const float*)d_in[12];
    float* out = (float*)d_out;

    __half *p_xh, *p_moeh, *p_atth, *p_ewh, *p_wqh, *p_wkh, *p_wvh, *p_woh;
    float *p_q, *p_k, *p_v;
    cudaGetSymbolAddress((void**)&p_xh,   g_xh);
    cudaGetSymbolAddress((void**)&p_moeh, g_moeh);
    cudaGetSymbolAddress((void**)&p_atth, g_atth);
    cudaGetSymbolAddress((void**)&p_ewh,  g_ewh);
    cudaGetSymbolAddress((void**)&p_wqh,  g_wqh);
    cudaGetSymbolAddress((void**)&p_wkh,  g_wkh);
    cudaGetSymbolAddress((void**)&p_wvh,  g_wvh);
    cudaGetSymbolAddress((void**)&p_woh,  g_woh);
    cudaGetSymbolAddress((void**)&p_q,    g_q);
    cudaGetSymbolAddress((void**)&p_k,    g_k);
    cudaGetSymbolAddress((void**)&p_v,    g_v);

    prep_kernel<<<1, 32>>>();
    router_kernel<<<NB, 128>>>(x, rw, rb);   // also writes g_xh (fp16 x)

    // fp32 -> fp16 weight converts (native layout; GEMM consumes k-major via ldmatrix.trans)
    cvt_kernel<<<2048, 256>>>(ew, p_ewh, (size_t)NE * NF * NU / 4);
    cvt_kernel<<<512, 256>>>(wq, p_wqh, (size_t)NU * NDM / 4);
    cvt_kernel<<<512, 256>>>(wk, p_wkh, (size_t)NU * NDM / 4);
    cvt_kernel<<<512, 256>>>(wv, p_wvh, (size_t)NU * NDM / 4);
    cvt_kernel<<<512, 256>>>(wo, p_woh, (size_t)NDM * NDM / 4);

    // sparse MoE (z = expert, y = token-tile, overprovisioned with early exit)
    gemm_kernel<true><<<dim3(NU / BN, NB / BM, NE), NTHREADS>>>(p_xh, p_ewh, eb, nullptr);
    combine_kernel<<<2048, 256>>>();

    gemm_kernel<false><<<dim3(NDM / BN, NB / BM), NTHREADS>>>(p_moeh, p_wqh, bq, p_q);
    gemm_kernel<false><<<dim3(NDM / BN, NB / BM), NTHREADS>>>(p_moeh, p_wkh, bk, p_k);
    gemm_kernel<false><<<dim3(NDM / BN, NB / BM), NTHREADS>>>(p_moeh, p_wvh, bv, p_v);

    attn_kernel<<<NB, 256>>>();

    gemm_kernel<false><<<dim3(NDM / BN, NB / BM), NTHREADS>>>(p_atth, p_woh, bo, out);
}

// round 8
// speedup vs baseline: 2.0940x; 1.0318x over previous
#include <cuda_runtime.h>
#include <cuda_fp16.h>
#include <cstdint>

// ---------------- problem dims ----------------
#define NB 8192
#define NF 2048
#define NE 16
#define NU 2048
#define NDM 2048
#define NH 16
#define QS (3 * NDM)   // fused QKV row stride

// ---------------- device scratch (static, no allocations) ----------------
__device__ __half g_xh  [(size_t)NB * NF];
__device__ __half g_moeh[(size_t)NB * NU];
__device__ float  g_p0  [(size_t)NB * NU];
__device__ float  g_p1  [(size_t)NB * NU];
__device__ float  g_qkv [(size_t)NB * QS];
__device__ __half g_atth[(size_t)NB * NDM];
__device__ __half g_ewh [(size_t)NE * NF * NU];   // fp16 expert weights, native [E][F][U]
__device__ __half g_wqkv[(size_t)NU * QS];        // fused [U][3*D] fp16
__device__ __half g_woh [(size_t)NDM * NDM];
__device__ float  g_bqkv[QS];
__device__ int    g_counts[NE];
__device__ int    g_rows [NE * NB];
__device__ float  g_gates[NE * NB];
__device__ unsigned char g_slots[NE * NB];

// ---------------- helpers ----------------
__device__ __forceinline__ uint32_t smem_u32(const void* p) {
    return (uint32_t)__cvta_generic_to_shared(p);
}
#define CPA16(dst, src) \
    asm volatile("cp.async.cg.shared.global [%0], [%1], 16;" :: "r"(dst), "l"(src))

__device__ __forceinline__ void mma16(float* c, const uint32_t* a, const uint32_t* b) {
    asm volatile(
        "mma.sync.aligned.m16n8k16.row.col.f32.f16.f16.f32 "
        "{%0,%1,%2,%3},{%4,%5,%6,%7},{%8,%9},{%0,%1,%2,%3};"
        : "+f"(c[0]), "+f"(c[1]), "+f"(c[2]), "+f"(c[3])
        : "r"(a[0]), "r"(a[1]), "r"(a[2]), "r"(a[3]), "r"(b[0]), "r"(b[1]));
}

#define LDSM4(r, addr) \
    asm volatile("ldmatrix.sync.aligned.m8n8.x4.shared.b16 {%0,%1,%2,%3}, [%4];" \
                 : "=r"((r)[0]), "=r"((r)[1]), "=r"((r)[2]), "=r"((r)[3]) : "r"(addr))
#define LDSM4T(r, addr) \
    asm volatile("ldmatrix.sync.aligned.m8n8.x4.trans.shared.b16 {%0,%1,%2,%3}, [%4];" \
                 : "=r"((r)[0]), "=r"((r)[1]), "=r"((r)[2]), "=r"((r)[3]) : "r"(addr))

// ---------------- prep kernels ----------------
__global__ void prep_kernel() {
    if (threadIdx.x < NE) g_counts[threadIdx.x] = 0;
}

// fp32 -> fp16 streaming convert
__global__ void cvt_kernel(const float* __restrict__ src, __half* __restrict__ dst, size_t n4) {
    const float4* s = (const float4*)src;
    uint2* d = (uint2*)dst;
    for (size_t i = (size_t)blockIdx.x * blockDim.x + threadIdx.x; i < n4;
         i += (size_t)gridDim.x * blockDim.x) {
        float4 v = s[i];
        __half2 lo = __floats2half2_rn(v.x, v.y);
        __half2 hi = __floats2half2_rn(v.z, v.w);
        uint2 o;
        o.x = *(uint32_t*)&lo;
        o.y = *(uint32_t*)&hi;
        d[i] = o;
    }
}

// fp32 [R][C] -> fp16 dst[r][dst_off + c] with dst row stride dld (concat converts)
__global__ void cvt_stride_kernel(const float* __restrict__ src, __half* __restrict__ dst,
                                  int R, int C, int dld, int dst_off) {
    size_t n4 = (size_t)R * C / 4;
    const float4* s = (const float4*)src;
    for (size_t i = (size_t)blockIdx.x * blockDim.x + threadIdx.x; i < n4;
         i += (size_t)gridDim.x * blockDim.x) {
        float4 v = s[i];
        size_t el = i * 4;
        int r = (int)(el / C), c = (int)(el % C);
        __half2 lo = __floats2half2_rn(v.x, v.y);
        __half2 hi = __floats2half2_rn(v.z, v.w);
        uint2 o;
        o.x = *(uint32_t*)&lo;
        o.y = *(uint32_t*)&hi;
        *(uint2*)(dst + (size_t)r * dld + dst_off + c) = o;
    }
}

__global__ void bias_concat_kernel(const float* __restrict__ b0, const float* __restrict__ b1,
                                   const float* __restrict__ b2) {
    int i = blockIdx.x * blockDim.x + threadIdx.x;
    if (i < NDM) {
        g_bqkv[i] = b0[i];
        g_bqkv[NDM + i] = b1[i];
        g_bqkv[2 * NDM + i] = b2[i];
    }
}

// combine MoE partial slots -> fp16 A operand for QKV GEMMs
__global__ void combine_kernel() {
    size_t n = (size_t)NB * NU / 4;
    const float4* a = (const float4*)g_p0;
    const float4* b = (const float4*)g_p1;
    uint2* d = (uint2*)g_moeh;
    for (size_t i = (size_t)blockIdx.x * blockDim.x + threadIdx.x; i < n;
         i += (size_t)gridDim.x * blockDim.x) {
        float4 u = a[i], w = b[i];
        __half2 lo = __floats2half2_rn(u.x + w.x, u.y + w.y);
        __half2 hi = __floats2half2_rn(u.z + w.z, u.w + w.w);
        uint2 o;
        o.x = *(uint32_t*)&lo;
        o.y = *(uint32_t*)&hi;
        d[i] = o;
    }
}

// ---------------- router: fp32 logits, softmax, top-2 + fused x->fp16 ----------------
__global__ void router_kernel(const float* __restrict__ x,
                              const float* __restrict__ rw,
                              const float* __restrict__ rb) {
    const int b = blockIdx.x;
    const int tid = threadIdx.x;  // 128 threads
    float part[NE];
#pragma unroll
    for (int e = 0; e < NE; e++) part[e] = 0.f;

    const float* xr = x + (size_t)b * NF;
    __half* xh = g_xh + (size_t)b * NF;
    for (int f = tid; f < NF; f += 128) {
        float xv = xr[f];
        xh[f] = __float2half_rn(xv);
        const float4* w4 = (const float4*)(rw + (size_t)f * NE);
#pragma unroll
        for (int e4 = 0; e4 < 4; e4++) {
            float4 w = w4[e4];
            part[e4 * 4 + 0] += xv * w.x;
            part[e4 * 4 + 1] += xv * w.y;
            part[e4 * 4 + 2] += xv * w.z;
            part[e4 * 4 + 3] += xv * w.w;
        }
    }

    __shared__ float red[NE][128];
#pragma unroll
    for (int e = 0; e < NE; e++) red[e][tid] = part[e];
    __syncthreads();

    __shared__ float lg[NE];
    if (tid < NE) {
        float s = 0.f;
        for (int j = 0; j < 128; j++) s += red[tid][j];
        lg[tid] = s + rb[tid];
    }
    __syncthreads();

    if (tid == 0) {
        float mx = lg[0];
#pragma unroll
        for (int e = 1; e < NE; e++) mx = fmaxf(mx, lg[e]);
        float p[NE];
        float s = 0.f;
#pragma unroll
        for (int e = 0; e < NE; e++) { p[e] = expf(lg[e] - mx); s += p[e]; }
        int e0 = 0; float b0 = p[0];
#pragma unroll
        for (int e = 1; e < NE; e++) if (p[e] > b0) { b0 = p[e]; e0 = e; }
        int e1 = -1; float b1 = -1.f;
#pragma unroll
        for (int e = 0; e < NE; e++)
            if (e != e0 && p[e] > b1) { b1 = p[e]; e1 = e; }
        float inv = 1.f / s;
        int pos = atomicAdd(&g_counts[e0], 1);
        g_rows [e0 * NB + pos] = b;
        g_gates[e0 * NB + pos] = b0 * inv;
        g_slots[e0 * NB + pos] = 0;
        pos = atomicAdd(&g_counts[e1], 1);
        g_rows [e1 * NB + pos] = b;
        g_gates[e1 * NB + pos] = b1 * inv;
        g_slots[e1 * NB + pos] = 1;
    }
}

// ---------------- fp16 GEMM: 128x128x64 tiles, ldmatrix + cp.async double buffer ----
#define BM 128
#define BN 128
#define BKK 64
#define LDA 72        // halves/row (144B): LDSM phases (addr/16)%8 = r%8, distinct
#define LDB2 136      // halves/row (272B): r*17%8 = r%8, distinct
#define NTHREADS 256
#define NKITER (NF / BKK)  // 32
#define A_BYTES (2 * BM * LDA * 2)     // 36864
#define B_BYTES (2 * BKK * LDB2 * 2)   // 34816
#define DYN_SMEM (A_BYTES + B_BYTES)   // 71680

template <bool MOE>
__global__ __launch_bounds__(NTHREADS) void gemm_kernel(
    const __half* __restrict__ A, const __half* __restrict__ B,
    const float* __restrict__ bias, float* __restrict__ C,
    int ldb, int ldc) {
    extern __shared__ char smraw[];
    __half (*As)[BM][LDA] = (__half (*)[BM][LDA])smraw;
    __half (*Bs)[BKK][LDB2] = (__half (*)[BKK][LDB2])(smraw + A_BYTES);
    __shared__ int rows_s[BM];
    __shared__ float gate_s[BM];
    __shared__ int slot_s[BM];

    const int tid = threadIdx.x;
    const int n0blk = blockIdx.x * BN;
    const int m0blk = blockIdx.y * BM;

    int cnt = BM;
    const __half* Bp = B;
    const float* biasp = bias;
    if (MOE) {
        const int e = blockIdx.z;
        const int ce = g_counts[e];
        cnt = ce - m0blk;
        if (cnt <= 0) return;
        if (cnt > BM) cnt = BM;
        Bp = B + (size_t)e * NF * NU;
        biasp = bias + e * NU;
        if (tid < BM) {
            bool v = tid < cnt;
            rows_s[tid] = v ? g_rows [e * NB + m0blk + tid] : 0;
            gate_s[tid] = v ? g_gates[e * NB + m0blk + tid] : 0.f;
            slot_s[tid] = v ? (int)g_slots[e * NB + m0blk + tid] : 0;
        }
        __syncthreads();
    }

    const int lane = tid & 31, warp = tid >> 5;
    const int wm = (warp >> 2) * 64;
    const int wn = (warp & 3) * 32;
    const int g = lane >> 2, tig = lane & 3;

    const int l15 = lane & 15;
    const int lhi = (lane >> 4) * 8;
    const uint32_t baseA = smem_u32(&As[0][0][0]);
    const uint32_t baseB = smem_u32(&Bs[0][0][0]);
    const uint32_t aoff = ((wm + l15) * LDA + lhi) * 2;
    const uint32_t boff = (l15 * LDB2 + wn + lhi) * 2;
    const uint32_t szA = BM * LDA * 2;
    const uint32_t szB = BKK * LDB2 * 2;

    float acc[4][4][4];
#pragma unroll
    for (int mt = 0; mt < 4; mt++)
#pragma unroll
        for (int nt = 0; nt < 4; nt++)
#pragma unroll
            for (int i = 0; i < 4; i++) acc[mt][nt][i] = 0.f;

    // A stage: 128 rows x 128B = 1024 x 16B chunks; B stage: 64 rows x 256B = 1024 chunks
    auto loadA = [&](int buf, int k0) {
#pragma unroll
        for (int i = 0; i < 4; i++) {
            int c = tid + i * NTHREADS;
            int m = c >> 3, hc = (c & 7) * 8;
            const __half* src;
            if (MOE) src = A + (size_t)rows_s[m] * NF + k0 + hc;
            else     src = A + (size_t)(m0blk + m) * NF + k0 + hc;
            CPA16(smem_u32(&As[buf][m][hc]), src);
        }
    };
    auto loadB = [&](int buf, int k0) {
#pragma unroll
        for (int i = 0; i < 4; i++) {
            int c = tid + i * NTHREADS;
            int kr = c >> 4, nc = (c & 15) * 8;
            CPA16(smem_u32(&Bs[buf][kr][nc]), Bp + (size_t)(k0 + kr) * ldb + n0blk + nc);
        }
    };

    loadA(0, 0);
    loadB(0, 0);
    asm volatile("cp.async.commit_group;");

    for (int kt = 0; kt < NKITER; kt++) {
        const int cb = kt & 1, nb2 = (kt + 1) & 1;
        if (kt + 1 < NKITER) { loadA(nb2, (kt + 1) * BKK); loadB(nb2, (kt + 1) * BKK); }
        asm volatile("cp.async.commit_group;");
        asm volatile("cp.async.wait_group 1;");
        __syncthreads();

        const uint32_t abase = baseA + cb * szA + aoff;
        const uint32_t bbase = baseB + cb * szB + boff;
#pragma unroll
        for (int ks = 0; ks < 4; ks++) {
            uint32_t a[4][4], b[2][4];
#pragma unroll
            for (int mt = 0; mt < 4; mt++)
                LDSM4(a[mt], abase + (mt * 16 * LDA + ks * 16) * 2);
#pragma unroll
            for (int ntp = 0; ntp < 2; ntp++)
                LDSM4T(b[ntp], bbase + (ks * 16 * LDB2 + ntp * 16) * 2);
#pragma unroll
            for (int mt = 0; mt < 4; mt++)
#pragma unroll
                for (int nt = 0; nt < 4; nt++)
                    mma16(acc[mt][nt], a[mt], &b[nt >> 1][(nt & 1) * 2]);
        }
        __syncthreads();
    }

#pragma unroll
    for (int mt = 0; mt < 4; mt++) {
#pragma unroll
        for (int nt = 0; nt < 4; nt++) {
            int r0 = wm + mt * 16 + g;
            int r1 = r0 + 8;
            int cg0 = n0blk + wn + nt * 8 + 2 * tig;
            int cg1 = cg0 + 1;
            float bz0 = biasp[cg0], bz1 = biasp[cg1];
            if (MOE) {
                if (r0 < cnt) {
                    int tok = rows_s[r0]; float gt = gate_s[r0];
                    float* dst = (slot_s[r0] ? g_p1 : g_p0) + (size_t)tok * NU;
                    dst[cg0] = gt * fmaxf(acc[mt][nt][0] + bz0, 0.f);
                    dst[cg1] = gt * fmaxf(acc[mt][nt][1] + bz1, 0.f);
                }
                if (r1 < cnt) {
                    int tok = rows_s[r1]; float gt = gate_s[r1];
                    float* dst = (slot_s[r1] ? g_p1 : g_p0) + (size_t)tok * NU;
                    dst[cg0] = gt * fmaxf(acc[mt][nt][2] + bz0, 0.f);
                    dst[cg1] = gt * fmaxf(acc[mt][nt][3] + bz1, 0.f);
                }
            } else {
                size_t ro0 = (size_t)(m0blk + r0) * ldc;
                size_t ro1 = (size_t)(m0blk + r1) * ldc;
                C[ro0 + cg0] = acc[mt][nt][0] + bz0;
                C[ro0 + cg1] = acc[mt][nt][1] + bz1;
                C[ro1 + cg0] = acc[mt][nt][2] + bz0;
                C[ro1 + cg1] = acc[mt][nt][3] + bz1;
            }
        }
    }
}

// ---------------- per-token single-latent attention (reads fused qkv) ------------
__global__ void attn_kernel() {
    const int b = blockIdx.x;
    const int tid = threadIdx.x;  // 256
    const int warp = tid >> 5, lane = tid & 31;

    __shared__ float sc[NH];
    const float* row = g_qkv + (size_t)b * QS;
    const float4* q4 = (const float4*)row;
    const float4* k4 = (const float4*)(row + NDM);
    const float4* v4 = (const float4*)(row + 2 * NDM);
    uint2* o4 = (uint2*)(g_atth + (size_t)b * NDM);

#pragma unroll
    for (int i = 0; i < 2; i++) {
        int h = warp * 2 + i;
        float4 qv = q4[h * 32 + lane];
        float4 kv = k4[h * 32 + lane];
        float s = qv.x * kv.x + qv.y * kv.y + qv.z * kv.z + qv.w * kv.w;
#pragma unroll
        for (int o = 16; o; o >>= 1) s += __shfl_xor_sync(0xffffffffu, s, o);
        if (lane == 0) sc[h] = s * 0.08838834764831845f;  // 1/sqrt(128)
    }
    __syncthreads();

    float mx = sc[0];
#pragma unroll
    for (int h = 1; h < NH; h++) mx = fmaxf(mx, sc[h]);
    float ssum = 0.f;
#pragma unroll
    for (int h = 0; h < NH; h++) ssum += expf(sc[h] - mx);
    float inv = 1.f / ssum;
    float a0 = expf(sc[warp] - mx) * inv;
    float a1 = expf(sc[warp + 8] - mx) * inv;

    {
        float4 vv = v4[tid];
        __half2 lo = __floats2half2_rn(a0 * vv.x, a0 * vv.y);
        __half2 hi = __floats2half2_rn(a0 * vv.z, a0 * vv.w);
        uint2 o; o.x = *(uint32_t*)&lo; o.y = *(uint32_t*)&hi;
        o4[tid] = o;
    }
    {
        float4 vv = v4[tid + 256];
        __half2 lo = __floats2half2_rn(a1 * vv.x, a1 * vv.y);
        __half2 hi = __floats2half2_rn(a1 * vv.z, a1 * vv.w);
        uint2 o; o.x = *(uint32_t*)&lo; o.y = *(uint32_t*)&hi;
        o4[tid + 256] = o;
    }
}

// ---------------- launcher ----------------
extern "C" void kernel_launch(void* const* d_in, const int* in_sizes, int n_in,
                              void* d_out, int out_size) {
    const float* x  = (const float*)d_in[0];
    const float* rw = (const float*)d_in[1];
    const float* rb = (const float*)d_in[2];
    const float* ew = (const float*)d_in[3];
    const float* eb = (const float*)d_in[4];
    const float* wq = (const float*)d_in[5];
    const float* bq = (const float*)d_in[6];
    const float* wk = (const float*)d_in[7];
    const float* bk = (const float*)d_in[8];
    const float* wv = (const float*)d_in[9];
    const float* bv = (const float*)d_in[10];
    const float* wo = (const float*)d_in[11];
    const float* bo = (const float*)d_in[12];
    float* out = (float*)d_out;

    cudaFuncSetAttribute(gemm_kernel<true>,  cudaFuncAttributeMaxDynamicSharedMemorySize, DYN_SMEM);
    cudaFuncSetAttribute(gemm_kernel<false>, cudaFuncAttributeMaxDynamicSharedMemorySize, DYN_SMEM);

    __half *p_xh, *p_moeh, *p_atth, *p_ewh, *p_wqkv, *p_woh;
    float *p_qkv, *p_bqkv;
    cudaGetSymbolAddress((void**)&p_xh,   g_xh);
    cudaGetSymbolAddress((void**)&p_moeh, g_moeh);
    cudaGetSymbolAddress((void**)&p_atth, g_atth);
    cudaGetSymbolAddress((void**)&p_ewh,  g_ewh);
    cudaGetSymbolAddress((void**)&p_wqkv, g_wqkv);
    cudaGetSymbolAddress((void**)&p_woh,  g_woh);
    cudaGetSymbolAddress((void**)&p_qkv,  g_qkv);
    cudaGetSymbolAddress((void**)&p_bqkv, g_bqkv);

    prep_kernel<<<1, 32>>>();
    router_kernel<<<NB, 128>>>(x, rw, rb);   // also writes g_xh (fp16 x)

    // weight converts (native layout; GEMM consumes k-major via ldmatrix.trans)
    cvt_kernel<<<2048, 256>>>(ew, p_ewh, (size_t)NE * NF * NU / 4);
    cvt_stride_kernel<<<512, 256>>>(wq, p_wqkv, NU, NDM, QS, 0);
    cvt_stride_kernel<<<512, 256>>>(wk, p_wqkv, NU, NDM, QS, NDM);
    cvt_stride_kernel<<<512, 256>>>(wv, p_wqkv, NU, NDM, QS, 2 * NDM);
    cvt_kernel<<<512, 256>>>(wo, p_woh, (size_t)NDM * NDM / 4);
    bias_concat_kernel<<<(NDM + 255) / 256, 256>>>(bq, bk, bv);

    // sparse MoE (z = expert, y = token-tile, overprovisioned with early exit)
    gemm_kernel<true><<<dim3(NU / BN, NB / BM, NE), NTHREADS, DYN_SMEM>>>(
        p_xh, p_ewh, eb, nullptr, NU, 0);
    combine_kernel<<<2048, 256>>>();

    // fused QKV GEMM: [8192 x 2048] @ [2048 x 6144]
    gemm_kernel<false><<<dim3(QS / BN, NB / BM), NTHREADS, DYN_SMEM>>>(
        p_moeh, p_wqkv, p_bqkv, p_qkv, QS, QS);

    attn_kernel<<<NB, 256>>>();

    gemm_kernel<false><<<dim3(NDM / BN, NB / BM), NTHREADS, DYN_SMEM>>>(
        p_atth, p_woh, bo, out, NDM, NDM);
}